// round 10
// baseline (speedup 1.0000x reference)
#include <cuda_runtime.h>
#include <cuda_bf16.h>
#include <stdint.h>

// ---------------------------------------------------------------------------
// weighted_loss: graph neighbor-state count -> key-grouped weighted CE
//
//   loss = sum_i nll_i * cnt(key_i)^(-1/2) / sum_i cnt(key_i)^(-1/2)
// regrouped by key:
//   num  = sum_keys cnt^(-1/2) * nllsum(key),   den = sum_keys cnt^(+1/2)
//
// Inputs (metadata order):
//   d_in[0] : out        float32 [N,2]
//   d_in[1] : x          int32   [N]      (binary 0/1)
//   d_in[2] : y          int32   [N]      (binary 0/1)
//   d_in[3] : edge_index int32   [2,E]    (row = ei[0:E], col = ei[E:2E])
// Output: scalar float32
//
// Replay-state contract: __device__ globals are zero at module load.
// g_cnt2 is re-zeroed by histnll (store-after-read); g_hcnt/g_hnll are
// zeroed at the top of edge_kernel (before any use). Every call sees
// identical initial state -> deterministic under graph replay.
// ---------------------------------------------------------------------------

#define MAXN   200704                 // >= N=200000, multiple of 16
#define HSIZE  (1 << 15)              // 32K keys (x:1 | s0:7 | s1:7), L2-hot

// Split per-node counters (400K distinct atomic addresses):
// [2i] = s1 (#nbr x==0), [2i+1] = s0 (#nbr x==1).
__device__ unsigned int g_cnt2[2 * MAXN];
__device__ int          g_hcnt[HSIZE];       // per-key node count
__device__ float        g_hnll[HSIZE];       // per-key nll sum

// ---------------------------------------------------------------------------
// Edge scatter: for each edge (r, c): ++g_cnt2[2r + (x[c]?1:0)]
// Builds the 196KB shared x byte-offset table straight from x (L2-broadcast),
// and zeroes the key tables for this call (they are first used by histnll).
__global__ void __launch_bounds__(1024, 1) edge_kernel(const int* __restrict__ ei,
                                                       const int* __restrict__ x,
                                                       int N, int E) {
    extern __shared__ unsigned char sx[];
    // build x byte-offset table in smem (int4 loads, uchar4 stores)
    {
        const int4* x4 = (const int4*)x;
        uchar4* dst = (uchar4*)sx;
        int n4i = N >> 2;
        for (int t = threadIdx.x; t < n4i; t += blockDim.x) {
            int4 xv = x4[t];
            uchar4 b;
            b.x = (xv.x > 0) ? 4 : 0;
            b.y = (xv.y > 0) ? 4 : 0;
            b.z = (xv.z > 0) ? 4 : 0;
            b.w = (xv.w > 0) ? 4 : 0;
            dst[t] = b;
        }
        // tail + pad to MAXN
        for (int i = (n4i << 2) + threadIdx.x; i < MAXN; i += blockDim.x)
            sx[i] = (i < N && x[i] > 0) ? 4 : 0;
    }
    // zero key tables (distributed across the grid; used only by later kernels)
    {
        uint4 z = make_uint4(0u, 0u, 0u, 0u);
        int total = HSIZE / 4;
        int gt = blockIdx.x * blockDim.x + threadIdx.x;
        int gs = gridDim.x * blockDim.x;
        for (int t = gt; t < total; t += gs) {
            ((uint4*)g_hcnt)[t] = z;
            ((uint4*)g_hnll)[t] = z;
        }
    }
    __syncthreads();

    unsigned long long base = (unsigned long long)(uintptr_t)(void*)g_cnt2;
    const int4* row4 = (const int4*)ei;
    const int4* col4 = (const int4*)(ei + E);
    int n4 = E >> 2;
    int tid    = blockIdx.x * blockDim.x + threadIdx.x;
    int stride = gridDim.x * blockDim.x;
    int sub = (threadIdx.x & 31) >> 2;          // 0..7: serialization group

    for (int i = tid; i < n4; i += stride) {
        int4 r = row4[i];
        int4 c = col4[i];
        unsigned long long a0 = base + (((unsigned long long)(unsigned)r.x) << 3) + sx[c.x];
        unsigned long long a1 = base + (((unsigned long long)(unsigned)r.y) << 3) + sx[c.y];
        unsigned long long a2 = base + (((unsigned long long)(unsigned)r.z) << 3) + sx[c.z];
        unsigned long long a3 = base + (((unsigned long long)(unsigned)r.w) << 3) + sx[c.w];
        #pragma unroll
        for (int k = 0; k < 8; k++) {
            asm volatile(
                "{\n\t"
                ".reg .pred q;\n\t"
                "setp.eq.s32 q, %0, %1;\n\t"
                "@q red.global.add.u32 [%2], 1;\n\t"
                "@q red.global.add.u32 [%3], 1;\n\t"
                "@q red.global.add.u32 [%4], 1;\n\t"
                "@q red.global.add.u32 [%5], 1;\n\t"
                "}"
                :: "r"(sub), "r"(k), "l"(a0), "l"(a1), "l"(a2), "l"(a3)
                : "memory");
        }
    }
    // tail (E not multiple of 4)
    if (blockIdx.x == 0 && threadIdx.x == 0) {
        const int* rowp = ei;
        const int* colp = ei + E;
        for (int i = n4 << 2; i < E; i++) {
            int r = rowp[i], c = colp[i];
            atomicAdd((unsigned int*)(uintptr_t)
                      (base + (((unsigned long long)(unsigned)r) << 3) + sx[c]), 1u);
        }
    }
}

// key = x<<14 | min(s0,127)<<7 | min(s1,127)
// (clamps unreachable: s ~ Poisson(32), P(s>=127) ~ e^-81)
__device__ __forceinline__ int make_key(int xv, int s0, int s1) {
    if (s0 > 127) s0 = 127;
    if (s1 > 127) s1 = 127;
    return ((xv > 0) ? (1 << 14) : 0) | (s0 << 7) | s1;
}

__device__ __forceinline__ float node_nll(float o0, float o1, int yv) {
    float m = fmaxf(o0, o1);
    float lse = m + __logf(__expf(o0 - m) + __expf(o1 - m));
    return lse - ((yv > 0) ? o1 : o0);
}

// Per-node: compute nll, accumulate (count, nll_sum) per key (2 nodes/thread).
// Re-zeroes g_cnt2 (store-after-read) so the next replay starts clean.
__global__ void histnll_kernel(const float* __restrict__ out2,
                               const int* __restrict__ x,
                               const int* __restrict__ y, int N) {
    int t = blockIdx.x * blockDim.x + threadIdx.x;
    int i = t * 2;
    if (i + 1 < N) {
        uint4  c  = ((const uint4*)g_cnt2)[t];  // node i: (s1,s0); node i+1: (s1,s0)
        float4 o  = ((const float4*)out2)[t];
        int2   yv = ((const int2*)y)[t];
        int2   xv = ((const int2*)x)[t];
        ((uint4*)g_cnt2)[t] = make_uint4(0u, 0u, 0u, 0u);   // reset for next call
        int k0 = make_key(xv.x, (int)c.y, (int)c.x);
        int k1 = make_key(xv.y, (int)c.w, (int)c.z);
        float n0 = node_nll(o.x, o.y, yv.x);
        float n1 = node_nll(o.z, o.w, yv.y);
        atomicAdd(&g_hcnt[k0], 1);
        atomicAdd(&g_hnll[k0], n0);
        atomicAdd(&g_hcnt[k1], 1);
        atomicAdd(&g_hnll[k1], n1);
    } else if (i < N) {
        int k = make_key(x[i], (int)g_cnt2[2 * i + 1], (int)g_cnt2[2 * i]);
        float n = node_nll(out2[2 * i], out2[2 * i + 1], y[i]);
        g_cnt2[2 * i] = 0u;
        g_cnt2[2 * i + 1] = 0u;
        atomicAdd(&g_hcnt[k], 1);
        atomicAdd(&g_hnll[k], n);
    }
}

__inline__ __device__ float warp_reduce(float v) {
    #pragma unroll
    for (int o = 16; o > 0; o >>= 1) v += __shfl_down_sync(0xFFFFFFFFu, v, o);
    return v;
}

// Reduce 32K keys with ONE 1024-thread block (32 independent loads in flight
// per thread; no cross-block atomics, no fence, no ticket).
__global__ void __launch_bounds__(1024) keyreduce_kernel(float* __restrict__ res) {
    float num = 0.0f, den = 0.0f;
    #pragma unroll 4
    for (int k = threadIdx.x; k < HSIZE; k += 1024) {
        int cnt = g_hcnt[k];
        if (cnt > 0) {
            float rs = rsqrtf((float)cnt);       // cnt^-1/2
            num += g_hnll[k] * rs;
            den += (float)cnt * rs;              // cnt^1/2
        }
    }
    __shared__ float snum[32], sden[32];
    int lane = threadIdx.x & 31, wid = threadIdx.x >> 5;
    num = warp_reduce(num);
    den = warp_reduce(den);
    if (lane == 0) { snum[wid] = num; sden[wid] = den; }
    __syncthreads();
    if (wid == 0) {
        num = snum[lane];
        den = sden[lane];
        num = warp_reduce(num);
        den = warp_reduce(den);
        if (lane == 0) res[0] = num / den;
    }
}

// ---------------------------------------------------------------------------
extern "C" void kernel_launch(void* const* d_in, const int* in_sizes, int n_in,
                              void* d_out, int out_size) {
    const float* out2 = (const float*)d_in[0];
    const int*   x    = (const int*)d_in[1];
    const int*   y    = (const int*)d_in[2];
    const int*   ei   = (const int*)d_in[3];
    float* res = (float*)d_out;

    int N = in_sizes[1];
    int E = in_sizes[3] / 2;

    static int sms = 0;
    if (sms == 0) {
        cudaDeviceGetAttribute(&sms, cudaDevAttrMultiProcessorCount, 0);
        cudaFuncSetAttribute(edge_kernel,
                             cudaFuncAttributeMaxDynamicSharedMemorySize, MAXN);
    }

    // 1. edge scatter (also builds smem x-table and zeroes key tables)
    edge_kernel<<<sms, 1024, MAXN>>>(ei, x, N, E);

    // 2. per-node nll + per-key accumulation (+ cnt2 reset for next replay)
    histnll_kernel<<<(N / 2 + 255) / 256, 256>>>(out2, x, y, N);

    // 3. single-block key reduction -> scalar
    keyreduce_kernel<<<1, 1024>>>(res);
}

// round 11
// speedup vs baseline: 1.0573x; 1.0573x over previous
#include <cuda_runtime.h>
#include <cuda_bf16.h>
#include <stdint.h>

// ---------------------------------------------------------------------------
// weighted_loss: graph neighbor-state count -> key-grouped weighted CE
//
//   loss = sum_i nll_i * cnt(key_i)^(-1/2) / sum_i cnt(key_i)^(-1/2)
// regrouped by key:
//   num  = sum_keys cnt^(-1/2) * nllsum(key),   den = sum_keys cnt^(+1/2)
//
// Inputs (metadata order):
//   d_in[0] : out        float32 [N,2]
//   d_in[1] : x          int32   [N]      (binary 0/1)
//   d_in[2] : y          int32   [N]      (binary 0/1)
//   d_in[3] : edge_index int32   [2,E]    (row = ei[0:E], col = ei[E:2E])
// Output: scalar float32
//
// Replay-state contract: __device__ globals are zero at module load.
// g_cnt2 is re-zeroed by histnll (store-after-read); g_hcnt/g_hnll and
// g_xbits are (re)written by init each call. Every call sees identical
// initial state -> deterministic under graph replay.
// ---------------------------------------------------------------------------

#define MAXN   200704                 // >= N=200000, multiple of 32
#define NBITW  (MAXN / 32)            // 6272 words = 25088 B bitmap
#define HSIZE  (1 << 15)              // 32K keys (x:1 | s0:7 | s1:7), L2-hot

// Split per-node counters (400K distinct atomic addresses):
// [2i] = s0 if bit=0 path... layout: g_cnt2[2r + xbit], xbit = x[col].
__device__ unsigned int g_cnt2[2 * MAXN];
__device__ int          g_hcnt[HSIZE];       // per-key node count
__device__ float        g_hnll[HSIZE];       // per-key nll sum
__device__ unsigned int g_xbits[NBITW];      // bit i = (x[i] > 0)

// ---------------------------------------------------------------------------
// Zero key tables + build x bitmap (ballot). One launch, covers N threads.
__global__ void init_kernel(const int* __restrict__ x, int N) {
    int i = blockIdx.x * blockDim.x + threadIdx.x;
    if (i < HSIZE / 4) {
        uint4 z = make_uint4(0u, 0u, 0u, 0u);
        ((uint4*)g_hcnt)[i] = z;
        ((uint4*)g_hnll)[i] = z;
    }
    int v = (i < N) ? (x[i] > 0) : 0;
    unsigned int bits = __ballot_sync(0xFFFFFFFFu, v);
    if ((threadIdx.x & 31) == 0) {
        int w = i >> 5;
        if (w < NBITW) g_xbits[w] = bits;
    }
}

// Edge scatter: for each edge (r, c): ++g_cnt2[2r + xbit(c)]
// 25KB x-bitmap in shared memory -> 2 CTAs x 1024 threads per SM (occ ~100%),
// doubling the warps feeding the L1tex wavefront queue vs the byte-table
// version (which was smem-capped at 1 CTA/SM, occ 49%).
__global__ void __launch_bounds__(1024, 2) edge_kernel(const int* __restrict__ ei,
                                                       int E) {
    __shared__ unsigned int sbits[NBITW];
    for (int w = threadIdx.x; w < NBITW; w += blockDim.x) sbits[w] = g_xbits[w];
    __syncthreads();

    const int4* row4 = (const int4*)ei;
    const int4* col4 = (const int4*)(ei + E);
    int n4 = E >> 2;
    int tid    = blockIdx.x * blockDim.x + threadIdx.x;
    int stride = gridDim.x * blockDim.x;

    for (int i = tid; i < n4; i += stride) {
        int4 r = row4[i];
        int4 c = col4[i];
        unsigned int b0 = (sbits[(unsigned)c.x >> 5] >> (c.x & 31)) & 1u;
        unsigned int b1 = (sbits[(unsigned)c.y >> 5] >> (c.y & 31)) & 1u;
        unsigned int b2 = (sbits[(unsigned)c.z >> 5] >> (c.z & 31)) & 1u;
        unsigned int b3 = (sbits[(unsigned)c.w >> 5] >> (c.w & 31)) & 1u;
        atomicAdd(&g_cnt2[(((unsigned)r.x) << 1) | b0], 1u);
        atomicAdd(&g_cnt2[(((unsigned)r.y) << 1) | b1], 1u);
        atomicAdd(&g_cnt2[(((unsigned)r.z) << 1) | b2], 1u);
        atomicAdd(&g_cnt2[(((unsigned)r.w) << 1) | b3], 1u);
    }
    // tail (E not multiple of 4)
    if (blockIdx.x == 0 && threadIdx.x == 0) {
        const int* rowp = ei;
        const int* colp = ei + E;
        for (int i = n4 << 2; i < E; i++) {
            int r = rowp[i], c = colp[i];
            unsigned int b = (sbits[(unsigned)c >> 5] >> (c & 31)) & 1u;
            atomicAdd(&g_cnt2[(((unsigned)r) << 1) | b], 1u);
        }
    }
}

// key = x<<14 | min(s0,127)<<7 | min(s1,127)
// s0 = #nbrs with x==1 (cnt2[2i+1]), s1 = #nbrs with x==0 (cnt2[2i]).
// (clamps unreachable: s ~ Poisson(32), P(s>=127) ~ e^-81)
__device__ __forceinline__ int make_key(int xv, int s0, int s1) {
    if (s0 > 127) s0 = 127;
    if (s1 > 127) s1 = 127;
    return ((xv > 0) ? (1 << 14) : 0) | (s0 << 7) | s1;
}

__device__ __forceinline__ float node_nll(float o0, float o1, int yv) {
    float m = fmaxf(o0, o1);
    float lse = m + __logf(__expf(o0 - m) + __expf(o1 - m));
    return lse - ((yv > 0) ? o1 : o0);
}

// Per-node: compute nll, accumulate (count, nll_sum) per key (2 nodes/thread).
// Re-zeroes g_cnt2 (store-after-read) so the next replay starts clean.
__global__ void histnll_kernel(const float* __restrict__ out2,
                               const int* __restrict__ x,
                               const int* __restrict__ y, int N) {
    int t = blockIdx.x * blockDim.x + threadIdx.x;
    int i = t * 2;
    if (i + 1 < N) {
        uint4  c  = ((const uint4*)g_cnt2)[t];  // node i: (c.x=s1@bit0? ...)
        float4 o  = ((const float4*)out2)[t];
        int2   yv = ((const int2*)y)[t];
        int2   xv = ((const int2*)x)[t];
        ((uint4*)g_cnt2)[t] = make_uint4(0u, 0u, 0u, 0u);   // reset for next call
        // layout: g_cnt2[2i] = bit0 (x==0 nbrs -> s1), g_cnt2[2i+1] = bit1 (s0)
        int k0 = make_key(xv.x, (int)c.y, (int)c.x);
        int k1 = make_key(xv.y, (int)c.w, (int)c.z);
        float n0 = node_nll(o.x, o.y, yv.x);
        float n1 = node_nll(o.z, o.w, yv.y);
        atomicAdd(&g_hcnt[k0], 1);
        atomicAdd(&g_hnll[k0], n0);
        atomicAdd(&g_hcnt[k1], 1);
        atomicAdd(&g_hnll[k1], n1);
    } else if (i < N) {
        int k = make_key(x[i], (int)g_cnt2[2 * i + 1], (int)g_cnt2[2 * i]);
        float n = node_nll(out2[2 * i], out2[2 * i + 1], y[i]);
        g_cnt2[2 * i] = 0u;
        g_cnt2[2 * i + 1] = 0u;
        atomicAdd(&g_hcnt[k], 1);
        atomicAdd(&g_hnll[k], n);
    }
}

__inline__ __device__ float warp_reduce(float v) {
    #pragma unroll
    for (int o = 16; o > 0; o >>= 1) v += __shfl_down_sync(0xFFFFFFFFu, v, o);
    return v;
}

// Reduce 32K keys with ONE 1024-thread block (32 independent loads in flight
// per thread; no cross-block atomics, no fence, no ticket).
__global__ void __launch_bounds__(1024) keyreduce_kernel(float* __restrict__ res) {
    float num = 0.0f, den = 0.0f;
    #pragma unroll 4
    for (int k = threadIdx.x; k < HSIZE; k += 1024) {
        int cnt = g_hcnt[k];
        if (cnt > 0) {
            float rs = rsqrtf((float)cnt);       // cnt^-1/2
            num += g_hnll[k] * rs;
            den += (float)cnt * rs;              // cnt^1/2
        }
    }
    __shared__ float snum[32], sden[32];
    int lane = threadIdx.x & 31, wid = threadIdx.x >> 5;
    num = warp_reduce(num);
    den = warp_reduce(den);
    if (lane == 0) { snum[wid] = num; sden[wid] = den; }
    __syncthreads();
    if (wid == 0) {
        num = snum[lane];
        den = sden[lane];
        num = warp_reduce(num);
        den = warp_reduce(den);
        if (lane == 0) res[0] = num / den;
    }
}

// ---------------------------------------------------------------------------
extern "C" void kernel_launch(void* const* d_in, const int* in_sizes, int n_in,
                              void* d_out, int out_size) {
    const float* out2 = (const float*)d_in[0];
    const int*   x    = (const int*)d_in[1];
    const int*   y    = (const int*)d_in[2];
    const int*   ei   = (const int*)d_in[3];
    float* res = (float*)d_out;

    int N = in_sizes[1];
    int E = in_sizes[3] / 2;

    static int sms = 0;
    if (sms == 0) {
        cudaDeviceGetAttribute(&sms, cudaDevAttrMultiProcessorCount, 0);
    }

    // 1. zero key tables + build x bitmap
    init_kernel<<<(N + 255) / 256, 256>>>(x, N);

    // 2. edge scatter: 2 CTAs/SM (25KB smem each), occ ~100%
    edge_kernel<<<2 * sms, 1024>>>(ei, E);

    // 3. per-node nll + per-key accumulation (+ cnt2 reset for next replay)
    histnll_kernel<<<(N / 2 + 255) / 256, 256>>>(out2, x, y, N);

    // 4. single-block key reduction -> scalar
    keyreduce_kernel<<<1, 1024>>>(res);
}

// round 12
// speedup vs baseline: 1.1045x; 1.0446x over previous
#include <cuda_runtime.h>
#include <cuda_bf16.h>
#include <stdint.h>

// ---------------------------------------------------------------------------
// weighted_loss: graph neighbor-state count -> key-grouped weighted CE
//
//   loss = sum_i nll_i * cnt(key_i)^(-1/2) / sum_i cnt(key_i)^(-1/2)
// regrouped by key:
//   num  = sum_keys cnt^(-1/2) * nllsum(key),   den = sum_keys cnt^(+1/2)
//
// Inputs (metadata order):
//   d_in[0] : out        float32 [N,2]
//   d_in[1] : x          int32   [N]      (binary 0/1)
//   d_in[2] : y          int32   [N]      (binary 0/1)
//   d_in[3] : edge_index int32   [2,E]    (row = ei[0:E], col = ei[E:2E])
// Output: scalar float32
//
// Replay-state contract: __device__ globals are zero at module load.
//   g_cnt2       : re-zeroed by histnll (store-after-read)
//   g_hcnt/g_hnll: re-zeroed by keyreduce (store-after-read)
//   g_acc/g_done : reset by keyreduce's last block
//   g_xbits      : rebuilt by init each call
// Every call sees identical initial state -> deterministic under replay.
// ---------------------------------------------------------------------------

#define MAXN   200704                 // >= N=200000, multiple of 32
#define NBITW  (MAXN / 32)            // 6272 words = 25088 B bitmap
#define HSIZE  (1 << 15)              // 32K keys (x:1 | s0:7 | s1:7), L2-hot

// Split per-node counters (400K distinct atomic addresses):
// g_cnt2[2r + xbit(c)]: [2i] = #nbrs with x==0 (s1), [2i+1] = #nbrs x==1 (s0)
__device__ unsigned int g_cnt2[2 * MAXN];
__device__ int          g_hcnt[HSIZE];       // per-key node count
__device__ float        g_hnll[HSIZE];       // per-key nll sum
__device__ unsigned int g_xbits[NBITW];      // bit i = (x[i] > 0)
__device__ double       g_acc[2];            // [0] = num, [1] = den
__device__ unsigned int g_done;              // last-block ticket

// ---------------------------------------------------------------------------
// Build x bitmap (ballot). Tiny kernel: read 800KB, write 25KB.
__global__ void init_kernel(const int* __restrict__ x, int N) {
    int i = blockIdx.x * blockDim.x + threadIdx.x;
    int v = (i < N) ? (x[i] > 0) : 0;
    unsigned int bits = __ballot_sync(0xFFFFFFFFu, v);
    if ((threadIdx.x & 31) == 0) {
        int w = i >> 5;
        if (w < NBITW) g_xbits[w] = bits;
    }
}

// Edge scatter: for each edge (r, c): ++g_cnt2[2r + xbit(c)]
// 25KB x-bitmap in shared memory -> 2 CTAs x 1024 threads per SM.
__global__ void __launch_bounds__(1024, 2) edge_kernel(const int* __restrict__ ei,
                                                       int E) {
    __shared__ unsigned int sbits[NBITW];
    for (int w = threadIdx.x; w < NBITW; w += blockDim.x) sbits[w] = g_xbits[w];
    __syncthreads();

    const int4* row4 = (const int4*)ei;
    const int4* col4 = (const int4*)(ei + E);
    int n4 = E >> 2;
    int tid    = blockIdx.x * blockDim.x + threadIdx.x;
    int stride = gridDim.x * blockDim.x;

    for (int i = tid; i < n4; i += stride) {
        int4 r = row4[i];
        int4 c = col4[i];
        unsigned int b0 = (sbits[(unsigned)c.x >> 5] >> (c.x & 31)) & 1u;
        unsigned int b1 = (sbits[(unsigned)c.y >> 5] >> (c.y & 31)) & 1u;
        unsigned int b2 = (sbits[(unsigned)c.z >> 5] >> (c.z & 31)) & 1u;
        unsigned int b3 = (sbits[(unsigned)c.w >> 5] >> (c.w & 31)) & 1u;
        atomicAdd(&g_cnt2[(((unsigned)r.x) << 1) | b0], 1u);
        atomicAdd(&g_cnt2[(((unsigned)r.y) << 1) | b1], 1u);
        atomicAdd(&g_cnt2[(((unsigned)r.z) << 1) | b2], 1u);
        atomicAdd(&g_cnt2[(((unsigned)r.w) << 1) | b3], 1u);
    }
    // tail (E not multiple of 4)
    if (blockIdx.x == 0 && threadIdx.x == 0) {
        const int* rowp = ei;
        const int* colp = ei + E;
        for (int i = n4 << 2; i < E; i++) {
            int r = rowp[i], c = colp[i];
            unsigned int b = (sbits[(unsigned)c >> 5] >> (c & 31)) & 1u;
            atomicAdd(&g_cnt2[(((unsigned)r) << 1) | b], 1u);
        }
    }
}

// key = x<<14 | min(s0,127)<<7 | min(s1,127)
// (clamps unreachable: s ~ Poisson(32), P(s>=127) ~ e^-81)
__device__ __forceinline__ int make_key(int xv, int s0, int s1) {
    if (s0 > 127) s0 = 127;
    if (s1 > 127) s1 = 127;
    return ((xv > 0) ? (1 << 14) : 0) | (s0 << 7) | s1;
}

__device__ __forceinline__ float node_nll(float o0, float o1, int yv) {
    float m = fmaxf(o0, o1);
    float lse = m + __logf(__expf(o0 - m) + __expf(o1 - m));
    return lse - ((yv > 0) ? o1 : o0);
}

// Per-node: compute nll, accumulate (count, nll_sum) per key (2 nodes/thread).
// Re-zeroes g_cnt2 (store-after-read) so the next replay starts clean.
__global__ void histnll_kernel(const float* __restrict__ out2,
                               const int* __restrict__ x,
                               const int* __restrict__ y, int N) {
    int t = blockIdx.x * blockDim.x + threadIdx.x;
    int i = t * 2;
    if (i + 1 < N) {
        uint4  c  = ((const uint4*)g_cnt2)[t];  // node i: (s1,s0); node i+1: (s1,s0)
        float4 o  = ((const float4*)out2)[t];
        int2   yv = ((const int2*)y)[t];
        int2   xv = ((const int2*)x)[t];
        ((uint4*)g_cnt2)[t] = make_uint4(0u, 0u, 0u, 0u);   // reset for next call
        int k0 = make_key(xv.x, (int)c.y, (int)c.x);
        int k1 = make_key(xv.y, (int)c.w, (int)c.z);
        float n0 = node_nll(o.x, o.y, yv.x);
        float n1 = node_nll(o.z, o.w, yv.y);
        atomicAdd(&g_hcnt[k0], 1);
        atomicAdd(&g_hnll[k0], n0);
        atomicAdd(&g_hcnt[k1], 1);
        atomicAdd(&g_hnll[k1], n1);
    } else if (i < N) {
        int k = make_key(x[i], (int)g_cnt2[2 * i + 1], (int)g_cnt2[2 * i]);
        float n = node_nll(out2[2 * i], out2[2 * i + 1], y[i]);
        g_cnt2[2 * i] = 0u;
        g_cnt2[2 * i + 1] = 0u;
        atomicAdd(&g_hcnt[k], 1);
        atomicAdd(&g_hnll[k], n);
    }
}

__inline__ __device__ float warp_reduce(float v) {
    #pragma unroll
    for (int o = 16; o > 0; o >>= 1) v += __shfl_down_sync(0xFFFFFFFFu, v, o);
    return v;
}

// Reduce 32K keys: 32 blocks x 256 threads, 4 keys per thread via uint4/float4.
// Re-zeroes the key tables (store-after-read). Last block writes the scalar.
__global__ void __launch_bounds__(256) keyreduce_kernel(float* __restrict__ res) {
    int t = blockIdx.x * blockDim.x + threadIdx.x;   // 8192 threads, 4 keys each
    float num = 0.0f, den = 0.0f;

    uint4   c4 = ((const uint4*)g_hcnt)[t];
    float4  n4 = ((const float4*)g_hnll)[t];
    ((uint4*)g_hcnt)[t]  = make_uint4(0u, 0u, 0u, 0u);  // reset for next call
    ((float4*)g_hnll)[t] = make_float4(0.f, 0.f, 0.f, 0.f);

    if (c4.x) { float rs = rsqrtf((float)c4.x); num += n4.x * rs; den += (float)c4.x * rs; }
    if (c4.y) { float rs = rsqrtf((float)c4.y); num += n4.y * rs; den += (float)c4.y * rs; }
    if (c4.z) { float rs = rsqrtf((float)c4.z); num += n4.z * rs; den += (float)c4.z * rs; }
    if (c4.w) { float rs = rsqrtf((float)c4.w); num += n4.w * rs; den += (float)c4.w * rs; }

    __shared__ float snum[8], sden[8];
    int lane = threadIdx.x & 31, wid = threadIdx.x >> 5;
    num = warp_reduce(num);
    den = warp_reduce(den);
    if (lane == 0) { snum[wid] = num; sden[wid] = den; }
    __syncthreads();
    if (wid == 0) {
        num = (lane < 8) ? snum[lane] : 0.0f;
        den = (lane < 8) ? sden[lane] : 0.0f;
        num = warp_reduce(num);
        den = warp_reduce(den);
        if (lane == 0) {
            atomicAdd(&g_acc[0], (double)num);
            atomicAdd(&g_acc[1], (double)den);
            __threadfence();
            unsigned int tk = atomicAdd(&g_done, 1u);
            if (tk == gridDim.x - 1) {
                double a = g_acc[0], b = g_acc[1];
                g_done = 0u;                 // reset for next graph replay
                g_acc[0] = 0.0;
                g_acc[1] = 0.0;
                res[0] = (float)(a / b);
            }
        }
    }
}

// ---------------------------------------------------------------------------
extern "C" void kernel_launch(void* const* d_in, const int* in_sizes, int n_in,
                              void* d_out, int out_size) {
    const float* out2 = (const float*)d_in[0];
    const int*   x    = (const int*)d_in[1];
    const int*   y    = (const int*)d_in[2];
    const int*   ei   = (const int*)d_in[3];
    float* res = (float*)d_out;

    int N = in_sizes[1];
    int E = in_sizes[3] / 2;

    static int sms = 0;
    if (sms == 0) {
        cudaDeviceGetAttribute(&sms, cudaDevAttrMultiProcessorCount, 0);
    }

    // 1. build x bitmap
    init_kernel<<<(N + 255) / 256, 256>>>(x, N);

    // 2. edge scatter: 2 CTAs/SM (25KB smem each)
    edge_kernel<<<2 * sms, 1024>>>(ei, E);

    // 3. per-node nll + per-key accumulation (+ cnt2 reset for next replay)
    histnll_kernel<<<(N / 2 + 255) / 256, 256>>>(out2, x, y, N);

    // 4. key-space reduction -> scalar (+ key-table reset for next replay)
    keyreduce_kernel<<<(HSIZE / 4) / 256, 256>>>(res);
}